// round 15
// baseline (speedup 1.0000x reference)
#include <cuda_runtime.h>
#include <math.h>
#include <stdint.h>

// Problem constants
#define BI   4
#define LSEQ 2048
#define DM   512
#define DI   1024      // d_inner
#define DS   16        // d_state
#define DTR  32        // dt_rank
#define NR   (BI*LSEQ) // 8192 rows (b*L flattened)

// ---------------- scratch (static device globals; no allocation) ----------------
__device__ float g_xz  [NR * 2 * DI];   // [row][2048]  x = [:1024], zs = silu(z) [1024:]
__device__ float g_xc  [2][NR * DI];    // conv+silu output per direction (dir-local time)
__device__ float g_xdbl[2][NR * 64];    // [row][64]: dt_r[0:32], B[32:48], C[48:64]
__device__ float g_xdbl_tf[2][NR * 64]; // tf32-rounded copy (dt GEMM A operand)
__device__ float g_dt  [2][NR * DI];    // softplus(dt) per direction
__device__ float g_y   [2][NR * DI];    // scan output per direction (dir-local time)

// pre-rounded (tf32) operands
__device__ float g_hid_tf [NR * DM];
__device__ float g_Win_tf [2 * DI * DM];
__device__ float g_Wx_tf  [2][64 * DI];
__device__ float g_Wdt_tf [2][DI * DTR];
__device__ float g_Wout_tf[DM * DI];

// ---------------- tf32 helpers ----------------
__device__ __forceinline__ float f2tf(float v) {
    uint32_t r; asm("cvt.rna.tf32.f32 %0, %1;" : "=r"(r) : "f"(v));
    return __uint_as_float(r);
}

__device__ __forceinline__ void mma8(float4& d, const uint32_t* a, const uint32_t* b) {
    asm volatile("mma.sync.aligned.m16n8k8.row.col.f32.tf32.tf32.f32 "
                 "{%0,%1,%2,%3}, {%4,%5,%6,%7}, {%8,%9}, {%0,%1,%2,%3};"
                 : "+f"(d.x), "+f"(d.y), "+f"(d.z), "+f"(d.w)
                 : "r"(a[0]), "r"(a[1]), "r"(a[2]), "r"(a[3]), "r"(b[0]), "r"(b[1]));
}

__device__ __forceinline__ float softplus_f(float t) {
    return (t > 20.f) ? t : log1pf(expf(t));
}

// ---------------- ONE fused tf32 pre-rounding kernel (all operands) ----------------
__global__ void round_all_kernel(const float* __restrict__ hidden,
                                 const float* __restrict__ W_in,
                                 const float* __restrict__ W_out,
                                 const float* __restrict__ Wx_f, const float* __restrict__ Wx_r,
                                 const float* __restrict__ Wdt_f, const float* __restrict__ Wdt_r)
{
    constexpr int S0 = NR * DM / 4;              // hidden
    constexpr int S1 = S0 + 2 * DI * DM / 4;     // W_in
    constexpr int S2 = S1 + 64 * DI / 4;         // Wx_f
    constexpr int S3 = S2 + 64 * DI / 4;         // Wx_r
    constexpr int S4 = S3 + DI * DTR / 4;        // Wdt_f
    constexpr int S5 = S4 + DI * DTR / 4;        // Wdt_r
    constexpr int S6 = S5 + DM * DI / 4;         // W_out

    int i = blockIdx.x * blockDim.x + threadIdx.x;
    if (i >= S6) return;

    const float* src; float* dst; int base;
    if      (i < S0) { src = hidden; dst = g_hid_tf;            base = 0;  }
    else if (i < S1) { src = W_in;   dst = g_Win_tf;            base = S0; }
    else if (i < S2) { src = Wx_f;   dst = g_Wx_tf[0];          base = S1; }
    else if (i < S3) { src = Wx_r;   dst = g_Wx_tf[1];          base = S2; }
    else if (i < S4) { src = Wdt_f;  dst = g_Wdt_tf[0];         base = S3; }
    else if (i < S5) { src = Wdt_r;  dst = g_Wdt_tf[1];         base = S4; }
    else             { src = W_out;  dst = g_Wout_tf;           base = S5; }

    int off = (i - base) * 4;
    float4 v = *(const float4*)&src[off];
    v.x = f2tf(v.x); v.y = f2tf(v.y); v.z = f2tf(v.z); v.w = f2tf(v.w);
    *(float4*)&dst[off] = v;
}

// ==================================================================================
// Single-pass tf32 tensor-core GEMM:  C[M,N] = A[M,K] @ W[N,K]^T
// Fragment-order shared memory; double-buffered stages; ONE __syncthreads per tile.
// EPI: 0 none, 1 softplus(acc+bias), 2 silu on columns >= DI (the z half of xz).
// DEPTH2: 2-deep register prefetch (latency window = two compute phases).
// ==================================================================================
template <int BN, int EPI, int FUSEA, int CVT_A, int DUAL, int DEPTH2>
__global__ void __launch_bounds__(256, 2)
gemm_tf32(const float* __restrict__ A, const float* __restrict__ A2, int lda,
          const float* __restrict__ W0, const float* __restrict__ W1,
          float* __restrict__ C, int M, int N, int K,
          const float* __restrict__ bias0, const float* __restrict__ bias1,
          long sA_stride, long sC_stride, float* __restrict__ C2)
{
    constexpr int BM = 128, BK = 16;
    constexpr int G  = BM / 16;
    constexpr int NT = BN / 16;
    constexpr int AV = BM / 64;
    constexpr int WV = BN / 64;
    constexpr int NS = DEPTH2 ? 2 : 1;     // register prefetch sets

    __shared__ float Afh[2][2][G][8][4][4];   // [stage][s][g][qid][tig'][slot]
    __shared__ float Bfh[2][2][BN][4][2];     // [stage][s][n][tig'][kh]

    const float* W    = blockIdx.z ? W1    : W0;
    const float* bias = blockIdx.z ? bias1 : bias0;
    A += (long)blockIdx.z * sA_stride;
    C += (long)blockIdx.z * sC_stride;
    if (DUAL) C2 += (long)blockIdx.z * sC_stride;

    const int tid  = threadIdx.x;
    const int warp = tid >> 5, lane = tid & 31;
    const int wrow = warp & 3, wcol = warp >> 2;
    const int rowBase = blockIdx.y * BM;
    const int colBase = blockIdx.x * BN;
    const int lr = tid >> 2;
    const int lk = (tid & 3) * 4;
    const int qid = lane >> 2, tig = lane & 3;

    const int sA  = lk >> 3;
    const int khA = (lk >> 2) & 1;

    float4 pa[NS][AV], pw[NS][WV];

    auto load_g = [&](int set, int k0) {
#pragma unroll
        for (int i = 0; i < AV; i++) {
            int r = rowBase + lr + 64 * i;
            float4 v = *(const float4*)&A[(size_t)r * lda + k0 + lk];
            if (FUSEA) {
                float4 v2 = *(const float4*)&A2[(size_t)(r ^ 2047) * lda + k0 + lk];
                v.x += v2.x; v.y += v2.y; v.z += v2.z; v.w += v2.w;
            }
            pa[set][i] = v;
        }
#pragma unroll
        for (int i = 0; i < WV; i++) {
            int r = colBase + lr + 64 * i;
            pw[set][i] = *(const float4*)&W[(size_t)r * K + k0 + lk];
        }
    };

    auto store_s = [&](int stg, int set) {
#pragma unroll
        for (int i = 0; i < AV; i++) {
            int r   = lr + 64 * i;
            int g   = r >> 4;
            int q   = r & 7;
            int slot = ((r >> 3) & 1) + 2 * khA;
            const float* v = &pa[set][i].x;
#pragma unroll
            for (int j = 0; j < 4; j++) {
                int jj = j ^ (q & 3) ^ (2 * sA);
                Afh[stg][sA][g][q][jj][slot] = CVT_A ? f2tf(v[j]) : v[j];
            }
        }
#pragma unroll
        for (int i = 0; i < WV; i++) {
            int n = lr + 64 * i;
            int cb = ((n & 1) << 1) ^ sA;
            const float* v = &pw[set][i].x;
#pragma unroll
            for (int j = 0; j < 4; j++) {
                int jj = j ^ cb;
                Bfh[stg][sA][n][jj][khA] = v[j];
            }
        }
    };

    float4 acc[2][NT];
#pragma unroll
    for (int mt = 0; mt < 2; mt++)
#pragma unroll
        for (int nt = 0; nt < NT; nt++) acc[mt][nt] = make_float4(0.f, 0.f, 0.f, 0.f);

    load_g(0, 0);
    store_s(0, 0);
    if (NS == 2 && BK < K) load_g(1, BK);
    __syncthreads();

    int it = 0;
    int k0 = 0;
    for (;;) {
        if (NS == 2) {
            if (k0 + 2 * BK < K) load_g(it & 1, k0 + 2 * BK);   // 2 tiles ahead
        } else {
            if (k0 + BK < K) load_g(0, k0 + BK);                // 1 tile ahead
        }

        const int buf = it & 1;
#pragma unroll
        for (int s = 0; s < 2; s++) {
            const int ptA = tig ^ (qid & 3) ^ (2 * s);
            uint32_t ah[2][4];
#pragma unroll
            for (int mt = 0; mt < 2; mt++) {
                int g = wrow * 2 + mt;
                *(uint4*)ah[mt] = *(const uint4*)&Afh[buf][s][g][qid][ptA][0];
            }
            const int ptB = tig ^ (((qid & 1) << 1) ^ s);
#pragma unroll
            for (int nt = 0; nt < NT; nt++) {
                int n = wcol * (BN / 2) + nt * 8 + qid;
                uint32_t bh[2];
                *(uint2*)bh = *(const uint2*)&Bfh[buf][s][n][ptB][0];
#pragma unroll
                for (int mt = 0; mt < 2; mt++)
                    mma8(acc[mt][nt], ah[mt], bh);
            }
        }

        if (k0 + BK >= K) break;
        store_s((it + 1) & 1, NS == 2 ? ((it + 1) & 1) : 0);
        __syncthreads();
        it++;
        k0 += BK;
    }

    // ---- epilogue ----
    const bool doz = (EPI == 2) && (colBase >= DI);   // z half of xz -> pre-apply silu
#pragma unroll
    for (int mt = 0; mt < 2; mt++) {
#pragma unroll
        for (int nt = 0; nt < NT; nt++) {
            int r0 = rowBase + wrow * 32 + mt * 16 + qid;
            int c  = colBase + wcol * (BN / 2) + nt * 8 + tig * 2;
            float4 v = acc[mt][nt];
            if (EPI == 1) {
                float b0 = bias[c], b1 = bias[c + 1];
                v.x = softplus_f(v.x + b0); v.y = softplus_f(v.y + b1);
                v.z = softplus_f(v.z + b0); v.w = softplus_f(v.w + b1);
            }
            if (EPI == 2 && doz) {
                v.x = v.x / (1.f + __expf(-v.x));
                v.y = v.y / (1.f + __expf(-v.y));
                v.z = v.z / (1.f + __expf(-v.z));
                v.w = v.w / (1.f + __expf(-v.w));
            }
            *(float2*)&C[(size_t)r0 * N + c]       = make_float2(v.x, v.y);
            *(float2*)&C[(size_t)(r0 + 8) * N + c] = make_float2(v.z, v.w);
            if (DUAL) {
                *(float2*)&C2[(size_t)r0 * N + c]       = make_float2(f2tf(v.x), f2tf(v.y));
                *(float2*)&C2[(size_t)(r0 + 8) * N + c] = make_float2(f2tf(v.z), f2tf(v.w));
            }
        }
    }
}

// ---------------- depthwise causal conv (K=4) + SiLU, both directions ----------------
__global__ void conv_silu_kernel(const float* __restrict__ cw_f, const float* __restrict__ cb_f,
                                 const float* __restrict__ cw_r, const float* __restrict__ cb_r)
{
    int idx = blockIdx.x * blockDim.x + threadIdx.x;
    if (idx >= 2 * NR * DI) return;
    int d   = idx % DI;
    int r   = (idx / DI) % NR;
    int dir = idx / (DI * NR);
    int b = r / LSEQ, t = r % LSEQ;

    const float* cw = dir ? cw_r : cw_f;
    const float* cb = dir ? cb_r : cb_f;

    float accv = cb[d];
#pragma unroll
    for (int k = 0; k < 4; k++) {
        int tt = t - 3 + k;
        if (tt >= 0) {
            int ts = dir ? (LSEQ - 1 - tt) : tt;
            accv += cw[d * 4 + k] * g_xz[(size_t)(b * LSEQ + ts) * (2 * DI) + d];
        }
    }
    float s = accv / (1.f + __expf(-accv));
    g_xc[dir][(size_t)r * DI + d] = s;
}

// ==================================================================================
// Selective scan v5: warp = 4 channels x 8 lanes, 2 states per lane.
// z arrives PRE-SILU'd from gemm1's epilogue -> no exp/div in the scan hot loop.
// SCAN_T=64 chunks, triple-buffered cp.async, one __syncthreads per chunk.
// ==================================================================================
#define SCAN_T 64
#define NCHUNK (LSEQ / SCAN_T)

__device__ __forceinline__ void cpa16(void* s, const void* g) {
    uint32_t sa = (uint32_t)__cvta_generic_to_shared(s);
    asm volatile("cp.async.ca.shared.global [%0], [%1], 16;" :: "r"(sa), "l"(g));
}
__device__ __forceinline__ void cpa_commit() {
    asm volatile("cp.async.commit_group;" ::: "memory");
}
__device__ __forceinline__ void cpa_wait1() {
    asm volatile("cp.async.wait_group 1;" ::: "memory");
}

__global__ void __launch_bounds__(256, 2)
scan_kernel(const float* __restrict__ Alog_f, const float* __restrict__ D_f,
            const float* __restrict__ Alog_r, const float* __restrict__ D_r)
{
    __shared__ __align__(16) float s_dt[3][SCAN_T][32];
    __shared__ __align__(16) float s_x [3][SCAN_T][32];
    __shared__ __align__(16) float s_z [3][SCAN_T][32];
    __shared__ __align__(16) float s_B [3][SCAN_T][16];
    __shared__ __align__(16) float s_C [3][SCAN_T][16];

    const int bx  = blockIdx.x;        // 0..255
    const int dir = bx >> 7;
    const int rem = bx & 127;
    const int b   = rem >> 5;          // 0..3
    const int d0  = (rem & 31) << 5;   // 32-channel group base

    const int tid  = threadIdx.x;
    const int w    = tid >> 5;
    const int lane = tid & 31;
    const int cc   = lane >> 3;        // channel within warp (0..3)
    const int j    = lane & 7;         // state-pair index (0..7)
    const int ch   = 4 * w + cc;       // local channel 0..31
    const int d    = d0 + ch;

    const float* Alog = dir ? Alog_r : Alog_f;
    const float* Dp   = dir ? D_r   : D_f;
    const float Av0 = -expf(Alog[d * DS + 2 * j]);
    const float Av1 = -expf(Alog[d * DS + 2 * j + 1]);
    const float Dd  = Dp[d];

    const float* dt_base = &g_dt[dir][(size_t)(b * LSEQ) * DI + d0];
    const float* x_base  = &g_xc[dir][(size_t)(b * LSEQ) * DI + d0];
    const float* bc_base = &g_xdbl[dir][(size_t)(b * LSEQ) * 64 + DTR];
    const float* z_base  = &g_xz[(size_t)(b * LSEQ) * (2 * DI) + DI + d0];  // pre-silu'd

    const int hbc = tid >> 7;          // 0 -> B, 1 -> C
    const int tl  = tid & 127;

    auto load_chunk = [&](int buf, int t0) {
#pragma unroll
        for (int q = 0; q < 2; q++) {
            int e  = q * 256 + tid;        // 0..511
            int tt = e >> 3;               // 0..63
            int lq4 = (e & 7) * 4;         // 0..28
            size_t row = (size_t)(t0 + tt);
            cpa16(&s_dt[buf][tt][lq4], dt_base + row * DI + lq4);
            cpa16(&s_x [buf][tt][lq4], x_base  + row * DI + lq4);
            int torig = dir ? (LSEQ - 1 - (t0 + tt)) : (t0 + tt);
            cpa16(&s_z [buf][tt][lq4], z_base + (size_t)torig * (2 * DI) + lq4);

            int e2  = q * 128 + tl;        // 0..255
            int tt2 = e2 >> 2;             // 0..63
            int lk4 = (e2 & 3) * 4;        // 0..12
            size_t row2 = (size_t)(t0 + tt2);
            if (hbc == 0) cpa16(&s_B[buf][tt2][lk4], bc_base + row2 * 64 + lk4);
            else          cpa16(&s_C[buf][tt2][lk4], bc_base + row2 * 64 + DS + lk4);
        }
        cpa_commit();
    };

    load_chunk(0, 0);
    load_chunk(1, SCAN_T);
    cpa_wait1();
    __syncthreads();

    float h0 = 0.f, h1 = 0.f;
    float* yp = &g_y[dir][(size_t)(b * LSEQ) * DI + d];

    int buf = 0;
    for (int chk = 0; chk < NCHUNK; chk++) {
#pragma unroll 8
        for (int tt = 0; tt < SCAN_T; tt++) {
            float dtv = s_dt[buf][tt][ch];
            float xv  = s_x [buf][tt][ch];
            float2 Bv = *(const float2*)&s_B[buf][tt][2 * j];
            float2 Cv = *(const float2*)&s_C[buf][tt][2 * j];

            float u = dtv * xv;
            h0 = __expf(dtv * Av0) * h0 + u * Bv.x;
            h1 = __expf(dtv * Av1) * h1 + u * Bv.y;

            float p = h0 * Cv.x + h1 * Cv.y;
            p += __shfl_xor_sync(0xffffffffu, p, 4);
            p += __shfl_xor_sync(0xffffffffu, p, 2);
            p += __shfl_xor_sync(0xffffffffu, p, 1);

            if (j == 0) {
                *yp = (p + Dd * xv) * s_z[buf][tt][ch];   // z already silu'd
            }
            yp += DI;
        }
        if (chk + 2 < NCHUNK) load_chunk((chk + 2) % 3, (chk + 2) * SCAN_T);
        else                  cpa_commit();
        cpa_wait1();
        __syncthreads();
        buf = (buf + 1) % 3;
    }
}

// ---------------- launch ----------------
extern "C" void kernel_launch(void* const* d_in, const int* in_sizes, int n_in,
                              void* d_out, int out_size)
{
    const float* hidden = (const float*)d_in[0];
    const float* W_in   = (const float*)d_in[1];
    const float* W_out  = (const float*)d_in[2];
    const float* cw_f   = (const float*)d_in[3];
    const float* cb_f   = (const float*)d_in[4];
    const float* Wx_f   = (const float*)d_in[5];
    const float* Wdt_f  = (const float*)d_in[6];
    const float* bdt_f  = (const float*)d_in[7];
    const float* Alog_f = (const float*)d_in[8];
    const float* D_f    = (const float*)d_in[9];
    const float* cw_r   = (const float*)d_in[10];
    const float* cb_r   = (const float*)d_in[11];
    const float* Wx_r   = (const float*)d_in[12];
    const float* Wdt_r  = (const float*)d_in[13];
    const float* bdt_r  = (const float*)d_in[14];
    const float* Alog_r = (const float*)d_in[15];
    const float* D_r    = (const float*)d_in[16];
    float* out = (float*)d_out;

    float* xz;      cudaGetSymbolAddress((void**)&xz,      g_xz);
    float* xc;      cudaGetSymbolAddress((void**)&xc,      g_xc);
    float* xdbl;    cudaGetSymbolAddress((void**)&xdbl,    g_xdbl);
    float* xdbl_tf; cudaGetSymbolAddress((void**)&xdbl_tf, g_xdbl_tf);
    float* dtb;     cudaGetSymbolAddress((void**)&dtb,     g_dt);
    float* yb;      cudaGetSymbolAddress((void**)&yb,      g_y);
    float* hid_tf;  cudaGetSymbolAddress((void**)&hid_tf,  g_hid_tf);
    float* Win_tf;  cudaGetSymbolAddress((void**)&Win_tf,  g_Win_tf);
    float* Wx_tf;   cudaGetSymbolAddress((void**)&Wx_tf,   g_Wx_tf);
    float* Wdt_tf;  cudaGetSymbolAddress((void**)&Wdt_tf,  g_Wdt_tf);
    float* Wout_tf; cudaGetSymbolAddress((void**)&Wout_tf, g_Wout_tf);

    // 0) ONE fused pre-rounding launch
    {
        constexpr int TOT4 = (NR * DM + 2 * DI * DM + 2 * 64 * DI + 2 * DI * DTR + DM * DI) / 4;
        round_all_kernel<<<(TOT4 + 255) / 256, 256>>>(hidden, W_in, W_out,
                                                      Wx_f, Wx_r, Wdt_f, Wdt_r);
    }

    // 1) xz = hidden @ W_in^T ; z half gets silu in epilogue (EPI=2)
    {
        dim3 grid((2 * DI) / 128, NR / 128, 1);
        gemm_tf32<128, 2, 0, 0, 0, 0><<<grid, 256>>>(hid_tf, nullptr, DM, Win_tf, nullptr, xz,
                                                     NR, 2 * DI, DM, nullptr, nullptr, 0, 0, nullptr);
    }

    // 2) conv + silu
    {
        int total = 2 * NR * DI;
        conv_silu_kernel<<<(total + 255) / 256, 256>>>(cw_f, cb_f, cw_r, cb_r);
    }

    // 3) x_dbl = xc @ W_x^T  (dirs batched on z; DUAL store; 2-deep prefetch)
    {
        dim3 grid(1, NR / 128, 2);
        gemm_tf32<64, 0, 0, 1, 1, 1><<<grid, 256>>>(xc, nullptr, DI, Wx_tf, Wx_tf + 64 * DI, xdbl,
                                                    NR, 64, DI, nullptr, nullptr,
                                                    (long)NR * DI, (long)NR * 64, xdbl_tf);
    }

    // 4) dt = softplus(dt_r @ W_dt^T + b_dt)
    {
        dim3 grid(DI / 128, NR / 128, 2);
        gemm_tf32<128, 1, 0, 0, 0, 0><<<grid, 256>>>(xdbl_tf, nullptr, 64, Wdt_tf, Wdt_tf + DI * DTR, dtb,
                                                     NR, DI, DTR, bdt_f, bdt_r,
                                                     (long)NR * 64, (long)NR * DI, nullptr);
    }

    // 5) selective scan
    scan_kernel<<<256, 256>>>(Alog_f, D_f, Alog_r, D_r);

    // 6+7) out = (y_fwd + reverse(y_rev)) @ W_out^T
    {
        dim3 grid(DM / 128, NR / 128, 1);
        gemm_tf32<128, 0, 1, 1, 0, 0><<<grid, 256>>>(yb, yb + (size_t)NR * DI, DI, Wout_tf, nullptr, out,
                                                     NR, DM, DI, nullptr, nullptr, 0, 0, nullptr);
    }
}

// round 16
// speedup vs baseline: 1.2000x; 1.2000x over previous
#include <cuda_runtime.h>
#include <math.h>
#include <stdint.h>

// Problem constants
#define BI   4
#define LSEQ 2048
#define DM   512
#define DI   1024      // d_inner
#define DS   16        // d_state
#define DTR  32        // dt_rank
#define NR   (BI*LSEQ) // 8192 rows (b*L flattened)

// ---------------- scratch (static device globals; no allocation) ----------------
__device__ float g_xz  [NR * 2 * DI];   // [row][2048]  x = [:1024], z = [1024:]
__device__ float g_xc  [2][NR * DI];    // conv+silu output per direction (dir-local time)
__device__ float g_xdbl[2][NR * 64];    // [row][64]: dt_r[0:32], B[32:48], C[48:64]
__device__ float g_xdbl_tf[2][NR * 64]; // tf32-rounded copy (dt GEMM A operand)
__device__ float g_dt  [2][NR * DI];    // softplus(dt) per direction
__device__ float g_y   [2][NR * DI];    // scan output per direction (dir-local time)

// pre-rounded (tf32) operands
__device__ float g_hid_tf [NR * DM];
__device__ float g_Win_tf [2 * DI * DM];
__device__ float g_Wx_tf  [2][64 * DI];
__device__ float g_Wdt_tf [2][DI * DTR];
__device__ float g_Wout_tf[DM * DI];

// ---------------- tf32 helpers ----------------
__device__ __forceinline__ float f2tf(float v) {
    uint32_t r; asm("cvt.rna.tf32.f32 %0, %1;" : "=r"(r) : "f"(v));
    return __uint_as_float(r);
}

__device__ __forceinline__ void mma8(float4& d, const uint32_t* a, const uint32_t* b) {
    asm volatile("mma.sync.aligned.m16n8k8.row.col.f32.tf32.tf32.f32 "
                 "{%0,%1,%2,%3}, {%4,%5,%6,%7}, {%8,%9}, {%0,%1,%2,%3};"
                 : "+f"(d.x), "+f"(d.y), "+f"(d.z), "+f"(d.w)
                 : "r"(a[0]), "r"(a[1]), "r"(a[2]), "r"(a[3]), "r"(b[0]), "r"(b[1]));
}

__device__ __forceinline__ float softplus_f(float t) {
    return (t > 20.f) ? t : log1pf(expf(t));
}

// ---------------- ONE fused tf32 pre-rounding kernel (all operands) ----------------
__global__ void round_all_kernel(const float* __restrict__ hidden,
                                 const float* __restrict__ W_in,
                                 const float* __restrict__ W_out,
                                 const float* __restrict__ Wx_f, const float* __restrict__ Wx_r,
                                 const float* __restrict__ Wdt_f, const float* __restrict__ Wdt_r)
{
    constexpr int S0 = NR * DM / 4;              // hidden
    constexpr int S1 = S0 + 2 * DI * DM / 4;     // W_in
    constexpr int S2 = S1 + 64 * DI / 4;         // Wx_f
    constexpr int S3 = S2 + 64 * DI / 4;         // Wx_r
    constexpr int S4 = S3 + DI * DTR / 4;        // Wdt_f
    constexpr int S5 = S4 + DI * DTR / 4;        // Wdt_r
    constexpr int S6 = S5 + DM * DI / 4;         // W_out

    int i = blockIdx.x * blockDim.x + threadIdx.x;
    if (i >= S6) return;

    const float* src; float* dst; int base;
    if      (i < S0) { src = hidden; dst = g_hid_tf;            base = 0;  }
    else if (i < S1) { src = W_in;   dst = g_Win_tf;            base = S0; }
    else if (i < S2) { src = Wx_f;   dst = g_Wx_tf[0];          base = S1; }
    else if (i < S3) { src = Wx_r;   dst = g_Wx_tf[1];          base = S2; }
    else if (i < S4) { src = Wdt_f;  dst = g_Wdt_tf[0];         base = S3; }
    else if (i < S5) { src = Wdt_r;  dst = g_Wdt_tf[1];         base = S4; }
    else             { src = W_out;  dst = g_Wout_tf;           base = S5; }

    int off = (i - base) * 4;
    float4 v = *(const float4*)&src[off];
    v.x = f2tf(v.x); v.y = f2tf(v.y); v.z = f2tf(v.z); v.w = f2tf(v.w);
    *(float4*)&dst[off] = v;
}

// ==================================================================================
// Single-pass tf32 tensor-core GEMM:  C[M,N] = A[M,K] @ W[N,K]^T
// Fragment-order shared memory; double-buffered stages; ONE __syncthreads per tile.
// BM templated: 128 (4 row-warp-groups x 2 col) or 64 (2 row-warp-groups x 4 col).
// W is ALWAYS pre-rounded tf32 (no cvt). A cvt only if CVT_A.
// DUAL: epilogue additionally writes tf32-rounded copy to C2.
// ==================================================================================
template <int BM, int BN, int EPI, int FUSEA, int CVT_A, int DUAL>
__global__ void __launch_bounds__(256, 2)
gemm_tf32(const float* __restrict__ A, const float* __restrict__ A2, int lda,
          const float* __restrict__ W0, const float* __restrict__ W1,
          float* __restrict__ C, int M, int N, int K,
          const float* __restrict__ bias0, const float* __restrict__ bias1,
          long sA_stride, long sC_stride, float* __restrict__ C2)
{
    constexpr int BK = 16;
    constexpr int G  = BM / 16;        // row-groups of 16
    constexpr int WR = BM / 32;        // warp rows (each warp spans 32 rows)
    constexpr int WC = 8 / WR;         // warp cols
    constexpr int NSPAN = BN / WC;     // columns per warp
    constexpr int NT = NSPAN / 8;      // 8-col tiles per warp
    constexpr int AV = BM / 64;        // float4 A loads per thread (>=1)
    constexpr int WV = BN / 64;        // float4 W loads per thread

    __shared__ float Afh[2][2][G][8][4][4];   // [stage][s][g][qid][tig'][slot]
    __shared__ float Bfh[2][2][BN][4][2];     // [stage][s][n][tig'][kh]

    const float* W    = blockIdx.z ? W1    : W0;
    const float* bias = blockIdx.z ? bias1 : bias0;
    A += (long)blockIdx.z * sA_stride;
    C += (long)blockIdx.z * sC_stride;
    if (DUAL) C2 += (long)blockIdx.z * sC_stride;

    const int tid  = threadIdx.x;
    const int warp = tid >> 5, lane = tid & 31;
    const int wrow = warp % WR, wcol = warp / WR;
    const int rowBase = blockIdx.y * BM;
    const int colBase = blockIdx.x * BN;
    const int lr = tid >> 2;           // 0..63
    const int lk = (tid & 3) * 4;      // 0,4,8,12
    const int qid = lane >> 2, tig = lane & 3;

    const int sA  = lk >> 3;           // which k8 step this thread stages
    const int khA = (lk >> 2) & 1;     // k half within step

    float4 pa[AV], pw[WV];

    auto load_g = [&](int k0) {
#pragma unroll
        for (int i = 0; i < AV; i++) {
            int r = rowBase + lr + 64 * i;
            float4 v = *(const float4*)&A[(size_t)r * lda + k0 + lk];
            if (FUSEA) {
                float4 v2 = *(const float4*)&A2[(size_t)(r ^ 2047) * lda + k0 + lk];
                v.x += v2.x; v.y += v2.y; v.z += v2.z; v.w += v2.w;
            }
            pa[i] = v;
        }
#pragma unroll
        for (int i = 0; i < WV; i++) {
            int r = colBase + lr + 64 * i;
            pw[i] = *(const float4*)&W[(size_t)r * K + k0 + lk];
        }
    };

    auto store_s = [&](int stg) {
#pragma unroll
        for (int i = 0; i < AV; i++) {
            int r   = lr + 64 * i;
            if (BM == 64 && r >= 64) continue;     // (unreachable; AV=1)
            int g   = r >> 4;
            int q   = r & 7;
            int slot = ((r >> 3) & 1) + 2 * khA;
            const float* v = &pa[i].x;
#pragma unroll
            for (int j = 0; j < 4; j++) {
                int jj = j ^ (q & 3) ^ (2 * sA);
                Afh[stg][sA][g][q][jj][slot] = CVT_A ? f2tf(v[j]) : v[j];
            }
        }
#pragma unroll
        for (int i = 0; i < WV; i++) {
            int n = lr + 64 * i;
            int cb = ((n & 1) << 1) ^ sA;
            const float* v = &pw[i].x;
#pragma unroll
            for (int j = 0; j < 4; j++) {
                int jj = j ^ cb;
                Bfh[stg][sA][n][jj][khA] = v[j];
            }
        }
    };

    float4 acc[2][NT];
#pragma unroll
    for (int mt = 0; mt < 2; mt++)
#pragma unroll
        for (int nt = 0; nt < NT; nt++) acc[mt][nt] = make_float4(0.f, 0.f, 0.f, 0.f);

    load_g(0);
    store_s(0);
    __syncthreads();

    int buf = 0;
    int k0 = 0;
    for (;;) {
        const bool has_next = (k0 + BK < K);
        if (has_next) load_g(k0 + BK);

#pragma unroll
        for (int s = 0; s < 2; s++) {
            const int ptA = tig ^ (qid & 3) ^ (2 * s);
            uint32_t ah[2][4];
#pragma unroll
            for (int mt = 0; mt < 2; mt++) {
                int g = wrow * 2 + mt;
                *(uint4*)ah[mt] = *(const uint4*)&Afh[buf][s][g][qid][ptA][0];
            }
            const int ptB = tig ^ (((qid & 1) << 1) ^ s);
#pragma unroll
            for (int nt = 0; nt < NT; nt++) {
                int n = wcol * NSPAN + nt * 8 + qid;
                uint32_t bh[2];
                *(uint2*)bh = *(const uint2*)&Bfh[buf][s][n][ptB][0];
#pragma unroll
                for (int mt = 0; mt < 2; mt++)
                    mma8(acc[mt][nt], ah[mt], bh);
            }
        }

        if (!has_next) break;
        store_s(buf ^ 1);
        __syncthreads();
        buf ^= 1;
        k0 += BK;
    }

    // ---- epilogue ----
#pragma unroll
    for (int mt = 0; mt < 2; mt++) {
#pragma unroll
        for (int nt = 0; nt < NT; nt++) {
            int r0 = rowBase + wrow * 32 + mt * 16 + qid;
            int c  = colBase + wcol * NSPAN + nt * 8 + tig * 2;
            float4 v = acc[mt][nt];
            if (EPI == 1) {
                float b0 = bias[c], b1 = bias[c + 1];
                v.x = softplus_f(v.x + b0); v.y = softplus_f(v.y + b1);
                v.z = softplus_f(v.z + b0); v.w = softplus_f(v.w + b1);
            }
            *(float2*)&C[(size_t)r0 * N + c]       = make_float2(v.x, v.y);
            *(float2*)&C[(size_t)(r0 + 8) * N + c] = make_float2(v.z, v.w);
            if (DUAL) {
                *(float2*)&C2[(size_t)r0 * N + c]       = make_float2(f2tf(v.x), f2tf(v.y));
                *(float2*)&C2[(size_t)(r0 + 8) * N + c] = make_float2(f2tf(v.z), f2tf(v.w));
            }
        }
    }
}

// ---------------- depthwise causal conv (K=4) + SiLU, float4 over d, both dirs ------
__global__ void conv_silu_kernel(const float* __restrict__ cw_f, const float* __restrict__ cb_f,
                                 const float* __restrict__ cw_r, const float* __restrict__ cb_r)
{
    constexpr int D4 = DI / 4;
    int idx = blockIdx.x * blockDim.x + threadIdx.x;
    if (idx >= 2 * NR * D4) return;
    int d4  = (idx % D4) * 4;
    int r   = (idx / D4) % NR;
    int dir = idx / (D4 * NR);
    int b = r / LSEQ, t = r % LSEQ;

    const float* cw = dir ? cw_r : cw_f;
    const float* cb = dir ? cb_r : cb_f;

    float4 acc = *(const float4*)&cb[d4];
    float4 w0 = *(const float4*)&cw[(d4 + 0) * 4];
    float4 w1 = *(const float4*)&cw[(d4 + 1) * 4];
    float4 w2 = *(const float4*)&cw[(d4 + 2) * 4];
    float4 w3 = *(const float4*)&cw[(d4 + 3) * 4];

#pragma unroll
    for (int k = 0; k < 4; k++) {
        int tt = t - 3 + k;
        if (tt >= 0) {
            int ts = dir ? (LSEQ - 1 - tt) : tt;
            float4 xv = *(const float4*)&g_xz[(size_t)(b * LSEQ + ts) * (2 * DI) + d4];
            acc.x += (&w0.x)[k] * xv.x;
            acc.y += (&w1.x)[k] * xv.y;
            acc.z += (&w2.x)[k] * xv.z;
            acc.w += (&w3.x)[k] * xv.w;
        }
    }
    acc.x = acc.x / (1.f + __expf(-acc.x));
    acc.y = acc.y / (1.f + __expf(-acc.y));
    acc.z = acc.z / (1.f + __expf(-acc.z));
    acc.w = acc.w / (1.f + __expf(-acc.w));
    *(float4*)&g_xc[dir][(size_t)r * DI + d4] = acc;
}

// ==================================================================================
// Selective scan v4: warp = 4 channels x 8 lanes, 2 states per lane.
// 256 blocks; SCAN_T=64 chunks, TRIPLE buffered; one __syncthreads per chunk.
// ==================================================================================
#define SCAN_T 64
#define NCHUNK (LSEQ / SCAN_T)

__device__ __forceinline__ void cpa16(void* s, const void* g) {
    uint32_t sa = (uint32_t)__cvta_generic_to_shared(s);
    asm volatile("cp.async.ca.shared.global [%0], [%1], 16;" :: "r"(sa), "l"(g));
}
__device__ __forceinline__ void cpa_commit() {
    asm volatile("cp.async.commit_group;" ::: "memory");
}
__device__ __forceinline__ void cpa_wait1() {
    asm volatile("cp.async.wait_group 1;" ::: "memory");
}

__global__ void __launch_bounds__(256, 2)
scan_kernel(const float* __restrict__ Alog_f, const float* __restrict__ D_f,
            const float* __restrict__ Alog_r, const float* __restrict__ D_r)
{
    __shared__ __align__(16) float s_dt[3][SCAN_T][32];
    __shared__ __align__(16) float s_x [3][SCAN_T][32];
    __shared__ __align__(16) float s_z [3][SCAN_T][32];
    __shared__ __align__(16) float s_B [3][SCAN_T][16];
    __shared__ __align__(16) float s_C [3][SCAN_T][16];

    const int bx  = blockIdx.x;        // 0..255
    const int dir = bx >> 7;
    const int rem = bx & 127;
    const int b   = rem >> 5;          // 0..3
    const int d0  = (rem & 31) << 5;   // 32-channel group base

    const int tid  = threadIdx.x;
    const int w    = tid >> 5;
    const int lane = tid & 31;
    const int cc   = lane >> 3;        // channel within warp (0..3)
    const int j    = lane & 7;         // state-pair index (0..7)
    const int ch   = 4 * w + cc;       // local channel 0..31
    const int d    = d0 + ch;

    const float* Alog = dir ? Alog_r : Alog_f;
    const float* Dp   = dir ? D_r   : D_f;
    const float Av0 = -expf(Alog[d * DS + 2 * j]);
    const float Av1 = -expf(Alog[d * DS + 2 * j + 1]);
    const float Dd  = Dp[d];

    const float* dt_base = &g_dt[dir][(size_t)(b * LSEQ) * DI + d0];
    const float* x_base  = &g_xc[dir][(size_t)(b * LSEQ) * DI + d0];
    const float* bc_base = &g_xdbl[dir][(size_t)(b * LSEQ) * 64 + DTR];
    const float* z_base  = &g_xz[(size_t)(b * LSEQ) * (2 * DI) + DI + d0];

    const int hbc = tid >> 7;          // 0 -> B, 1 -> C
    const int tl  = tid & 127;

    auto load_chunk = [&](int buf, int t0) {
#pragma unroll
        for (int q = 0; q < 2; q++) {
            int e  = q * 256 + tid;        // 0..511
            int tt = e >> 3;               // 0..63
            int lq4 = (e & 7) * 4;         // 0..28
            size_t row = (size_t)(t0 + tt);
            cpa16(&s_dt[buf][tt][lq4], dt_base + row * DI + lq4);
            cpa16(&s_x [buf][tt][lq4], x_base  + row * DI + lq4);
            int torig = dir ? (LSEQ - 1 - (t0 + tt)) : (t0 + tt);
            cpa16(&s_z [buf][tt][lq4], z_base + (size_t)torig * (2 * DI) + lq4);

            int e2  = q * 128 + tl;        // 0..255
            int tt2 = e2 >> 2;             // 0..63
            int lk4 = (e2 & 3) * 4;        // 0..12
            size_t row2 = (size_t)(t0 + tt2);
            if (hbc == 0) cpa16(&s_B[buf][tt2][lk4], bc_base + row2 * 64 + lk4);
            else          cpa16(&s_C[buf][tt2][lk4], bc_base + row2 * 64 + DS + lk4);
        }
        cpa_commit();
    };

    load_chunk(0, 0);
    load_chunk(1, SCAN_T);
    cpa_wait1();
    __syncthreads();

    float h0 = 0.f, h1 = 0.f;
    float* yp = &g_y[dir][(size_t)(b * LSEQ) * DI + d];

    int buf = 0;
    for (int chk = 0; chk < NCHUNK; chk++) {
#pragma unroll 8
        for (int tt = 0; tt < SCAN_T; tt++) {
            float dtv = s_dt[buf][tt][ch];
            float xv  = s_x [buf][tt][ch];
            float2 Bv = *(const float2*)&s_B[buf][tt][2 * j];
            float2 Cv = *(const float2*)&s_C[buf][tt][2 * j];

            float u = dtv * xv;
            h0 = __expf(dtv * Av0) * h0 + u * Bv.x;
            h1 = __expf(dtv * Av1) * h1 + u * Bv.y;

            float p = h0 * Cv.x + h1 * Cv.y;
            p += __shfl_xor_sync(0xffffffffu, p, 4);
            p += __shfl_xor_sync(0xffffffffu, p, 2);
            p += __shfl_xor_sync(0xffffffffu, p, 1);

            if (j == 0) {
                float zv = s_z[buf][tt][ch];
                float zs = zv / (1.f + __expf(-zv));
                *yp = (p + Dd * xv) * zs;
            }
            yp += DI;
        }
        if (chk + 2 < NCHUNK) load_chunk((chk + 2) % 3, (chk + 2) * SCAN_T);
        else                  cpa_commit();
        cpa_wait1();
        __syncthreads();
        buf = (buf + 1) % 3;
    }
}

// ---------------- launch ----------------
extern "C" void kernel_launch(void* const* d_in, const int* in_sizes, int n_in,
                              void* d_out, int out_size)
{
    const float* hidden = (const float*)d_in[0];
    const float* W_in   = (const float*)d_in[1];
    const float* W_out  = (const float*)d_in[2];
    const float* cw_f   = (const float*)d_in[3];
    const float* cb_f   = (const float*)d_in[4];
    const float* Wx_f   = (const float*)d_in[5];
    const float* Wdt_f  = (const float*)d_in[6];
    const float* bdt_f  = (const float*)d_in[7];
    const float* Alog_f = (const float*)d_in[8];
    const float* D_f    = (const float*)d_in[9];
    const float* cw_r   = (const float*)d_in[10];
    const float* cb_r   = (const float*)d_in[11];
    const float* Wx_r   = (const float*)d_in[12];
    const float* Wdt_r  = (const float*)d_in[13];
    const float* bdt_r  = (const float*)d_in[14];
    const float* Alog_r = (const float*)d_in[15];
    const float* D_r    = (const float*)d_in[16];
    float* out = (float*)d_out;

    float* xz;      cudaGetSymbolAddress((void**)&xz,      g_xz);
    float* xc;      cudaGetSymbolAddress((void**)&xc,      g_xc);
    float* xdbl;    cudaGetSymbolAddress((void**)&xdbl,    g_xdbl);
    float* xdbl_tf; cudaGetSymbolAddress((void**)&xdbl_tf, g_xdbl_tf);
    float* dtb;     cudaGetSymbolAddress((void**)&dtb,     g_dt);
    float* yb;      cudaGetSymbolAddress((void**)&yb,      g_y);
    float* hid_tf;  cudaGetSymbolAddress((void**)&hid_tf,  g_hid_tf);
    float* Win_tf;  cudaGetSymbolAddress((void**)&Win_tf,  g_Win_tf);
    float* Wx_tf;   cudaGetSymbolAddress((void**)&Wx_tf,   g_Wx_tf);
    float* Wdt_tf;  cudaGetSymbolAddress((void**)&Wdt_tf,  g_Wdt_tf);
    float* Wout_tf; cudaGetSymbolAddress((void**)&Wout_tf, g_Wout_tf);

    // 0) ONE fused pre-rounding launch
    {
        constexpr int TOT4 = (NR * DM + 2 * DI * DM + 2 * 64 * DI + 2 * DI * DTR + DM * DI) / 4;
        round_all_kernel<<<(TOT4 + 255) / 256, 256>>>(hidden, W_in, W_out,
                                                      Wx_f, Wx_r, Wdt_f, Wdt_r);
    }

    // 1) xz = hidden @ W_in^T
    {
        dim3 grid((2 * DI) / 128, NR / 128, 1);
        gemm_tf32<128, 128, 0, 0, 0, 0><<<grid, 256>>>(hid_tf, nullptr, DM, Win_tf, nullptr, xz,
                                                       NR, 2 * DI, DM, nullptr, nullptr, 0, 0, nullptr);
    }

    // 2) conv + silu (float4 over d)
    {
        int total = 2 * NR * (DI / 4);
        conv_silu_kernel<<<(total + 255) / 256, 256>>>(cw_f, cb_f, cw_r, cb_r);
    }

    // 3) x_dbl = xc @ W_x^T  (BM=64 -> 256 CTAs; dirs batched on z; DUAL store)
    {
        dim3 grid(1, NR / 64, 2);
        gemm_tf32<64, 64, 0, 0, 1, 1><<<grid, 256>>>(xc, nullptr, DI, Wx_tf, Wx_tf + 64 * DI, xdbl,
                                                     NR, 64, DI, nullptr, nullptr,
                                                     (long)NR * DI, (long)NR * 64, xdbl_tf);
    }

    // 4) dt = softplus(dt_r @ W_dt^T + b_dt)
    {
        dim3 grid(DI / 128, NR / 128, 2);
        gemm_tf32<128, 128, 1, 0, 0, 0><<<grid, 256>>>(xdbl_tf, nullptr, 64, Wdt_tf, Wdt_tf + DI * DTR, dtb,
                                                       NR, DI, DTR, bdt_f, bdt_r,
                                                       (long)NR * 64, (long)NR * DI, nullptr);
    }

    // 5) selective scan
    scan_kernel<<<256, 256>>>(Alog_f, D_f, Alog_r, D_r);

    // 6+7) out = (y_fwd + reverse(y_rev)) @ W_out^T
    {
        dim3 grid(DM / 128, NR / 128, 1);
        gemm_tf32<128, 128, 0, 1, 1, 0><<<grid, 256>>>(yb, yb + (size_t)NR * DI, DI, Wout_tf, nullptr, out,
                                                       NR, DM, DI, nullptr, nullptr, 0, 0, nullptr);
    }
}